// round 10
// baseline (speedup 1.0000x reference)
#include <cuda_runtime.h>
#include <cstdint>

#define NODES 20000
#define BATCH 32
#define FEAT  64
#define OUTD  64
#define EIG   16

// --- phase-1 pipeline geometry ---
#define CBLK    50            // node-chunks (grid.y)
#define MPB     400           // m per block  (CBLK*MPB == NODES)
#define MT      40            // m per pipeline stage
#define NSTG    4             // stages resident (3 in flight while computing)
#define NSTAGES (MPB / MT)    // 10

// Scratch (device globals — no allocation allowed)
__device__ float g_zpart[CBLK * BATCH * FEAT * EIG];  // 6.55 MB partials
__device__ float g_z[BATCH * FEAT * EIG];             // 128 KB
__device__ float g_w[BATCH * OUTD * EIG];             // 128 KB

__device__ __forceinline__ uint32_t s2u(const void* p) {
    return (uint32_t)__cvta_generic_to_shared(p);
}
// ---- packed f32x2 helpers (PTX-only; doubles fp32 FMA throughput) ----
__device__ __forceinline__ unsigned long long pack2(float a, float b) {
    unsigned long long r;
    asm("mov.b64 %0, {%1, %2};" : "=l"(r) : "f"(a), "f"(b));
    return r;
}
__device__ __forceinline__ void unpack2(unsigned long long v, float& a, float& b) {
    asm("mov.b64 {%0, %1}, %2;" : "=f"(a), "=f"(b) : "l"(v));
}
__device__ __forceinline__ unsigned long long fma2(unsigned long long a,
                                                   unsigned long long b,
                                                   unsigned long long c) {
    unsigned long long d;
    asm("fma.rn.f32x2 %0, %1, %2, %3;" : "=l"(d) : "l"(a), "l"(b), "l"(c));
    return d;
}

// ---------------------------------------------------------------------------
// ncu-alignment no-ops: put k_project at process-launch #6 (capture slot).
// ---------------------------------------------------------------------------
__global__ void k_nop() {
    if (threadIdx.x == 0xFFFFFFFFu) g_z[0] = 0.f;  // never taken
}

// ---------------------------------------------------------------------------
// Phase 1: z[b,i,f] = sum_m V[m,f] * x[m_global, f] ... cp.async pipeline
// (R8-proven) + FFMA2 mainloop; NSTG=4 -> deeper in-flight window.
// grid (BATCH, CBLK), 256 thr.
// ---------------------------------------------------------------------------
__global__ void __launch_bounds__(256) k_project(const float* __restrict__ x,
                                                 const float* __restrict__ V) {
    __shared__ __align__(16) float sbuf[NSTG * MT * FEAT + NSTG * MT * EIG]; // 51.2 KB
    float* sx = sbuf;                          // [NSTG][MT][FEAT]
    float* sv = sbuf + NSTG * MT * FEAT;       // [NSTG][MT][EIG]

    const int b = blockIdx.x, c = blockIdx.y;
    const int t  = threadIdx.x;
    const int i4 = t & 15;          // i = 4*i4 .. +3
    const int fh = (t >> 4) & 1;    // f-half: f = fh*8 .. +7
    const int mg = t >> 5;          // m-group 0..7 (5 m per stage)

    const int m0 = c * MPB;
    const float* xbase = x + ((size_t)b * NODES + m0) * FEAT;
    const float* vbase = V + (size_t)m0 * EIG;

    auto load_stage = [&](int s) {
        const int st = s % NSTG;
        const int mb = s * MT;
        #pragma unroll
        for (int q = t; q < MT * FEAT / 4; q += 256) {       // 640 float4
            const int m = q >> 4, iq = q & 15;
            const float* src = xbase + (size_t)(mb + m) * FEAT + iq * 4;
            uint32_t dst = s2u(&sx[(st * MT + m) * FEAT + iq * 4]);
            asm volatile("cp.async.cg.shared.global [%0], [%1], 16;\n"
                         :: "r"(dst), "l"(src));
        }
        if (t < MT * EIG / 4) {                              // 160 float4
            const int m = t >> 2, e4 = t & 3;
            const float* src = vbase + (mb + m) * EIG + e4 * 4;
            uint32_t dst = s2u(&sv[(st * MT + m) * EIG + e4 * 4]);
            asm volatile("cp.async.cg.shared.global [%0], [%1], 16;\n"
                         :: "r"(dst), "l"(src));
        }
    };

    unsigned long long acc2[4][4];  // [i][f-pair]
    #pragma unroll
    for (int a = 0; a < 4; ++a)
        #pragma unroll
        for (int p = 0; p < 4; ++p) acc2[a][p] = pack2(0.f, 0.f);

    #pragma unroll
    for (int s = 0; s < NSTG - 1; ++s) {
        load_stage(s);
        asm volatile("cp.async.commit_group;\n");
    }

    for (int s = 0; s < NSTAGES; ++s) {
        if (s + NSTG - 1 < NSTAGES) load_stage(s + NSTG - 1);
        asm volatile("cp.async.commit_group;\n");
        asm volatile("cp.async.wait_group %0;\n" :: "n"(NSTG - 1));
        __syncthreads();

        const int st = s % NSTG;
        #pragma unroll
        for (int mm = 0; mm < MT / 8; ++mm) {
            const int m = mg * (MT / 8) + mm;
            float4 x4 = *(const float4*)&sx[(st * MT + m) * FEAT + i4 * 4];
            ulonglong2 va = *(const ulonglong2*)&sv[(st * MT + m) * EIG + fh * 8];
            unsigned long long xd0 = pack2(x4.x, x4.x);
            unsigned long long xd1 = pack2(x4.y, x4.y);
            unsigned long long xd2 = pack2(x4.z, x4.z);
            unsigned long long xd3 = pack2(x4.w, x4.w);
            acc2[0][0] = fma2(xd0, va.x, acc2[0][0]);
            acc2[0][1] = fma2(xd0, va.y, acc2[0][1]);
            acc2[1][0] = fma2(xd1, va.x, acc2[1][0]);
            acc2[1][1] = fma2(xd1, va.y, acc2[1][1]);
            acc2[2][0] = fma2(xd2, va.x, acc2[2][0]);
            acc2[2][1] = fma2(xd2, va.y, acc2[2][1]);
            acc2[3][0] = fma2(xd3, va.x, acc2[3][0]);
            acc2[3][1] = fma2(xd3, va.y, acc2[3][1]);
            ulonglong2 vb = *(const ulonglong2*)&sv[(st * MT + m) * EIG + fh * 8 + 4];
            acc2[0][2] = fma2(xd0, vb.x, acc2[0][2]);
            acc2[0][3] = fma2(xd0, vb.y, acc2[0][3]);
            acc2[1][2] = fma2(xd1, vb.x, acc2[1][2]);
            acc2[1][3] = fma2(xd1, vb.y, acc2[1][3]);
            acc2[2][2] = fma2(xd2, vb.x, acc2[2][2]);
            acc2[2][3] = fma2(xd2, vb.y, acc2[2][3]);
            acc2[3][2] = fma2(xd3, vb.x, acc2[3][2]);
            acc2[3][3] = fma2(xd3, vb.y, acc2[3][3]);
        }
        __syncthreads();
    }

    // cross-mg reduction: overlay 8 x 1024 floats on sbuf
    asm volatile("cp.async.wait_group 0;\n");
    __syncthreads();
    #pragma unroll
    for (int a = 0; a < 4; ++a)
        #pragma unroll
        for (int p = 0; p < 4; ++p) {
            float lo, hi;
            unpack2(acc2[a][p], lo, hi);
            *(float2*)&sbuf[mg * 1024 + (4 * i4 + a) * EIG + fh * 8 + 2 * p] =
                make_float2(lo, hi);
        }
    __syncthreads();

    const int o = t * 4;   // 256 threads x 4 floats = 1024 outputs
    float4 r = make_float4(0.f, 0.f, 0.f, 0.f);
    #pragma unroll
    for (int g2 = 0; g2 < 8; ++g2) {
        float4 p = *(const float4*)&sbuf[g2 * 1024 + o];
        r.x += p.x; r.y += p.y; r.z += p.z; r.w += p.w;
    }
    *(float4*)&g_zpart[((size_t)c * BATCH + b) * 1024 + o] = r;
}

// ---------------------------------------------------------------------------
// Reduce chunk partials: z = sum_c zpart[c]   (6.55 MB, L2-resident)
// ---------------------------------------------------------------------------
__global__ void __launch_bounds__(128) k_reduce() {
    const int idx = blockIdx.x * 128 + threadIdx.x;  // 32768 threads total
    float s = 0.f;
    #pragma unroll 10
    for (int c = 0; c < CBLK; ++c)
        s += g_zpart[c * (BATCH * FEAT * EIG) + idx];
    g_z[idx] = s;
}

// ---------------------------------------------------------------------------
// Phase 2 (R6-proven): w[b,j,e] = sum_n G-interleaved * z. Coalesced z loads,
// G register-cached. grid (OUTD, 2), 512 threads = 16 warps (warp = e).
// ---------------------------------------------------------------------------
__global__ void __launch_bounds__(512) k_filter(const float* __restrict__ G) {
    const int j  = blockIdx.x;
    const int bh = blockIdx.y;
    const int e  = threadIdx.x >> 5;
    const int l  = threadIdx.x & 31;

    const float* Gp = G + (size_t)j * (FEAT * EIG * EIG)
                        + (l >> 2) * (EIG * EIG) + e * EIG + (l & 3) * 4;
    float4 g[8];
    #pragma unroll
    for (int k = 0; k < 8; ++k)
        g[k] = *(const float4*)(Gp + k * 8 * (EIG * EIG));

    const int b0 = bh * 16;
    #pragma unroll 2
    for (int bb = 0; bb < 16; ++bb) {
        const int b = b0 + bb;
        const float* zb = g_z + b * (FEAT * EIG) + 4 * l;
        float acc = 0.f;
        #pragma unroll
        for (int k = 0; k < 8; ++k) {
            float4 z4 = *(const float4*)(zb + k * 128);
            acc += g[k].x * z4.x + g[k].y * z4.y + g[k].z * z4.z + g[k].w * z4.w;
        }
        #pragma unroll
        for (int off = 16; off > 0; off >>= 1)
            acc += __shfl_down_sync(0xffffffffu, acc, off);
        if (l == 0) g_w[(b * OUTD + j) * EIG + e] = acc;
    }
}

// ---------------------------------------------------------------------------
// Phase 3 (R9-proven + swt removal): out[b,n,j] = sum_e V[n,e] * w[b,j,e]
// Lane owns j-pair (2l, 2l+1); w-cache built DIRECTLY from g_w (L2-hot;
// 2x float4 per e-quad) -- no smem transpose, one less __syncthreads.
// grid (50, BATCH), 256 thr = 8 warps; warp handles 50 consecutive nodes.
// ---------------------------------------------------------------------------
#define NTILE2 400
__global__ void __launch_bounds__(256, 4) k_output(const float* __restrict__ V,
                                                   float* __restrict__ out) {
    const int tile = blockIdx.x, b = blockIdx.y;
    const int t = threadIdx.x;
    const int lane = t & 31, wid = t >> 5;

    __shared__ __align__(16) float vt[NTILE2 * EIG];        // 25.6 KB [n][e]

    const int n0 = tile * NTILE2;

    // V rows n0..n0+399 -> vt[n][e]  (NODES = 50*400 exactly; no bounds)
    for (int k = t; k < NTILE2 * EIG / 4; k += 256)
        *(float4*)&vt[k * 4] = *(const float4*)&V[(size_t)n0 * EIG + k * 4];

    // lane's j-pair (2l, 2l+1) w-cache from gmem: rows are 16 floats apart
    const float* wbase = g_w + ((size_t)b * OUTD + 2 * lane) * EIG;
    unsigned long long wp[EIG];
    #pragma unroll
    for (int q = 0; q < 4; ++q) {
        float4 w0 = *(const float4*)(wbase + 4 * q);          // j = 2l
        float4 w1 = *(const float4*)(wbase + EIG + 4 * q);    // j = 2l+1
        wp[4*q+0] = pack2(w0.x, w1.x);
        wp[4*q+1] = pack2(w0.y, w1.y);
        wp[4*q+2] = pack2(w0.z, w1.z);
        wp[4*q+3] = pack2(w0.w, w1.w);
    }
    __syncthreads();

    const int nw0 = wid * 50;
    float* ob = out + ((size_t)b * NODES + n0 + nw0) * OUTD + lane * 2;

    for (int s = 0; s < 50; ++s) {
        const float* vp = &vt[(nw0 + s) * EIG];
        unsigned long long a0 = pack2(0.f, 0.f), a1 = pack2(0.f, 0.f);

        float4 va = *(const float4*)(vp);
        a0 = fma2(pack2(va.x, va.x), wp[0], a0);
        a1 = fma2(pack2(va.y, va.y), wp[1], a1);
        a0 = fma2(pack2(va.z, va.z), wp[2], a0);
        a1 = fma2(pack2(va.w, va.w), wp[3], a1);
        float4 vb = *(const float4*)(vp + 4);
        a0 = fma2(pack2(vb.x, vb.x), wp[4], a0);
        a1 = fma2(pack2(vb.y, vb.y), wp[5], a1);
        a0 = fma2(pack2(vb.z, vb.z), wp[6], a0);
        a1 = fma2(pack2(vb.w, vb.w), wp[7], a1);
        float4 vc = *(const float4*)(vp + 8);
        a0 = fma2(pack2(vc.x, vc.x), wp[8], a0);
        a1 = fma2(pack2(vc.y, vc.y), wp[9], a1);
        a0 = fma2(pack2(vc.z, vc.z), wp[10], a0);
        a1 = fma2(pack2(vc.w, vc.w), wp[11], a1);
        float4 vd = *(const float4*)(vp + 12);
        a0 = fma2(pack2(vd.x, vd.x), wp[12], a0);
        a1 = fma2(pack2(vd.y, vd.y), wp[13], a1);
        a0 = fma2(pack2(vd.z, vd.z), wp[14], a0);
        a1 = fma2(pack2(vd.w, vd.w), wp[15], a1);

        float x0, x1, y0, y1;
        unpack2(a0, x0, x1);
        unpack2(a1, y0, y1);
        *(float2*)(ob + (size_t)s * OUTD) = make_float2(x0 + y0, x1 + y1);
    }
}

extern "C" void kernel_launch(void* const* d_in, const int* in_sizes, int n_in,
                              void* d_out, int out_size) {
    const float* x = (const float*)d_in[0];   // (32, 20000, 64)
    const float* V = (const float*)d_in[1];   // (20000, 16)
    const float* G = (const float*)d_in[2];   // (64, 64, 16, 16)
    float* out = (float*)d_out;               // (32, 20000, 64)

    // ncu capture alignment: k_project is the 4th launch here (#6 in process)
    k_nop<<<1, 32>>>();
    k_nop<<<1, 32>>>();
    k_nop<<<1, 32>>>();

    k_project<<<dim3(BATCH, CBLK), 256>>>(x, V);
    k_reduce<<<256, 128>>>();
    k_filter<<<dim3(OUTD, 2), 512>>>(G);
    k_output<<<dim3(CBLK, BATCH), 256>>>(V, out);
}

// round 11
// speedup vs baseline: 1.1515x; 1.1515x over previous
#include <cuda_runtime.h>
#include <cstdint>

#define NODES 20000
#define BATCH 32
#define FEAT  64
#define OUTD  64
#define EIG   16

// --- phase-1 pipeline geometry (R7/R9-proven) ---
#define CBLK    50            // node-chunks (grid.y)
#define MPB     400           // m per block  (CBLK*MPB == NODES)
#define MT      40            // m per pipeline stage
#define NSTG    3             // stages resident
#define NSTAGES (MPB / MT)    // 10

// Scratch (device globals — no allocation allowed)
__device__ float g_zpart[CBLK * BATCH * FEAT * EIG];  // 6.55 MB partials
__device__ float g_z[BATCH * FEAT * EIG];             // 128 KB
__device__ float g_w[BATCH * OUTD * EIG];             // 128 KB

__device__ __forceinline__ uint32_t s2u(const void* p) {
    return (uint32_t)__cvta_generic_to_shared(p);
}
// ---- packed f32x2 helpers (PTX-only; doubles fp32 FMA throughput) ----
__device__ __forceinline__ unsigned long long pack2(float a, float b) {
    unsigned long long r;
    asm("mov.b64 %0, {%1, %2};" : "=l"(r) : "f"(a), "f"(b));
    return r;
}
__device__ __forceinline__ void unpack2(unsigned long long v, float& a, float& b) {
    asm("mov.b64 {%0, %1}, %2;" : "=f"(a), "=f"(b) : "l"(v));
}
__device__ __forceinline__ unsigned long long fma2(unsigned long long a,
                                                   unsigned long long b,
                                                   unsigned long long c) {
    unsigned long long d;
    asm("fma.rn.f32x2 %0, %1, %2, %3;" : "=l"(d) : "l"(a), "l"(b), "l"(c));
    return d;
}

// ---------------------------------------------------------------------------
// Phase 1: z[b,i,f] = sum_m V[m,f] * x[b,m,i]
// cp.async pipeline + FFMA2 mainloop. OCCUPANCY FIX: __launch_bounds__(256,4)
// caps regs at 64 (R10 profile: 68 regs -> only 3 blocks/SM resident;
// 64 regs -> 4 blocks/SM, 32 warps, occ 50%). grid (BATCH, CBLK), 256 thr.
// ---------------------------------------------------------------------------
__global__ void __launch_bounds__(256, 4) k_project(const float* __restrict__ x,
                                                    const float* __restrict__ V) {
    __shared__ __align__(16) float sbuf[NSTG * MT * FEAT + NSTG * MT * EIG]; // 38.4 KB
    float* sx = sbuf;                          // [NSTG][MT][FEAT]
    float* sv = sbuf + NSTG * MT * FEAT;       // [NSTG][MT][EIG]

    const int b = blockIdx.x, c = blockIdx.y;
    const int t  = threadIdx.x;
    const int i4 = t & 15;          // i = 4*i4 .. +3
    const int fh = (t >> 4) & 1;    // f-half: f = fh*8 .. +7
    const int mg = t >> 5;          // m-group 0..7 (5 m per stage)

    const int m0 = c * MPB;
    const float* xbase = x + ((size_t)b * NODES + m0) * FEAT;
    const float* vbase = V + (size_t)m0 * EIG;

    auto load_stage = [&](int s) {
        const int st = s % NSTG;
        const int mb = s * MT;
        #pragma unroll
        for (int q = t; q < MT * FEAT / 4; q += 256) {       // 640 float4
            const int m = q >> 4, iq = q & 15;
            const float* src = xbase + (size_t)(mb + m) * FEAT + iq * 4;
            uint32_t dst = s2u(&sx[(st * MT + m) * FEAT + iq * 4]);
            asm volatile("cp.async.cg.shared.global [%0], [%1], 16;\n"
                         :: "r"(dst), "l"(src));
        }
        if (t < MT * EIG / 4) {                              // 160 float4
            const int m = t >> 2, e4 = t & 3;
            const float* src = vbase + (mb + m) * EIG + e4 * 4;
            uint32_t dst = s2u(&sv[(st * MT + m) * EIG + e4 * 4]);
            asm volatile("cp.async.cg.shared.global [%0], [%1], 16;\n"
                         :: "r"(dst), "l"(src));
        }
    };

    unsigned long long acc2[4][4];  // [i][f-pair]
    #pragma unroll
    for (int a = 0; a < 4; ++a)
        #pragma unroll
        for (int p = 0; p < 4; ++p) acc2[a][p] = pack2(0.f, 0.f);

    #pragma unroll
    for (int s = 0; s < NSTG - 1; ++s) {
        load_stage(s);
        asm volatile("cp.async.commit_group;\n");
    }

    for (int s = 0; s < NSTAGES; ++s) {
        if (s + NSTG - 1 < NSTAGES) load_stage(s + NSTG - 1);
        asm volatile("cp.async.commit_group;\n");
        asm volatile("cp.async.wait_group %0;\n" :: "n"(NSTG - 1));
        __syncthreads();

        const int st = s % NSTG;
        #pragma unroll
        for (int mm = 0; mm < MT / 8; ++mm) {
            const int m = mg * (MT / 8) + mm;
            float4 x4 = *(const float4*)&sx[(st * MT + m) * FEAT + i4 * 4];
            ulonglong2 va = *(const ulonglong2*)&sv[(st * MT + m) * EIG + fh * 8];
            unsigned long long xd0 = pack2(x4.x, x4.x);
            unsigned long long xd1 = pack2(x4.y, x4.y);
            unsigned long long xd2 = pack2(x4.z, x4.z);
            unsigned long long xd3 = pack2(x4.w, x4.w);
            acc2[0][0] = fma2(xd0, va.x, acc2[0][0]);
            acc2[0][1] = fma2(xd0, va.y, acc2[0][1]);
            acc2[1][0] = fma2(xd1, va.x, acc2[1][0]);
            acc2[1][1] = fma2(xd1, va.y, acc2[1][1]);
            acc2[2][0] = fma2(xd2, va.x, acc2[2][0]);
            acc2[2][1] = fma2(xd2, va.y, acc2[2][1]);
            acc2[3][0] = fma2(xd3, va.x, acc2[3][0]);
            acc2[3][1] = fma2(xd3, va.y, acc2[3][1]);
            ulonglong2 vb = *(const ulonglong2*)&sv[(st * MT + m) * EIG + fh * 8 + 4];
            acc2[0][2] = fma2(xd0, vb.x, acc2[0][2]);
            acc2[0][3] = fma2(xd0, vb.y, acc2[0][3]);
            acc2[1][2] = fma2(xd1, vb.x, acc2[1][2]);
            acc2[1][3] = fma2(xd1, vb.y, acc2[1][3]);
            acc2[2][2] = fma2(xd2, vb.x, acc2[2][2]);
            acc2[2][3] = fma2(xd2, vb.y, acc2[2][3]);
            acc2[3][2] = fma2(xd3, vb.x, acc2[3][2]);
            acc2[3][3] = fma2(xd3, vb.y, acc2[3][3]);
        }
        __syncthreads();
    }

    // cross-mg reduction: overlay 8 x 1024 floats on sbuf
    asm volatile("cp.async.wait_group 0;\n");
    __syncthreads();
    #pragma unroll
    for (int a = 0; a < 4; ++a)
        #pragma unroll
        for (int p = 0; p < 4; ++p) {
            float lo, hi;
            unpack2(acc2[a][p], lo, hi);
            *(float2*)&sbuf[mg * 1024 + (4 * i4 + a) * EIG + fh * 8 + 2 * p] =
                make_float2(lo, hi);
        }
    __syncthreads();

    const int o = t * 4;   // 256 threads x 4 floats = 1024 outputs
    float4 r = make_float4(0.f, 0.f, 0.f, 0.f);
    #pragma unroll
    for (int g2 = 0; g2 < 8; ++g2) {
        float4 p = *(const float4*)&sbuf[g2 * 1024 + o];
        r.x += p.x; r.y += p.y; r.z += p.z; r.w += p.w;
    }
    *(float4*)&g_zpart[((size_t)c * BATCH + b) * 1024 + o] = r;
}

// ---------------------------------------------------------------------------
// Reduce chunk partials: z = sum_c zpart[c]   (6.55 MB, L2-resident)
// ---------------------------------------------------------------------------
__global__ void __launch_bounds__(128) k_reduce() {
    const int idx = blockIdx.x * 128 + threadIdx.x;  // 32768 threads total
    float s = 0.f;
    #pragma unroll 10
    for (int c = 0; c < CBLK; ++c)
        s += g_zpart[c * (BATCH * FEAT * EIG) + idx];
    g_z[idx] = s;
}

// ---------------------------------------------------------------------------
// Phase 2 (R6-proven): w[b,j,e] = sum_n G-interleaved * z. Coalesced z loads,
// G register-cached. grid (OUTD, 2), 512 threads = 16 warps (warp = e).
// ---------------------------------------------------------------------------
__global__ void __launch_bounds__(512) k_filter(const float* __restrict__ G) {
    const int j  = blockIdx.x;
    const int bh = blockIdx.y;
    const int e  = threadIdx.x >> 5;
    const int l  = threadIdx.x & 31;

    const float* Gp = G + (size_t)j * (FEAT * EIG * EIG)
                        + (l >> 2) * (EIG * EIG) + e * EIG + (l & 3) * 4;
    float4 g[8];
    #pragma unroll
    for (int k = 0; k < 8; ++k)
        g[k] = *(const float4*)(Gp + k * 8 * (EIG * EIG));

    const int b0 = bh * 16;
    #pragma unroll 2
    for (int bb = 0; bb < 16; ++bb) {
        const int b = b0 + bb;
        const float* zb = g_z + b * (FEAT * EIG) + 4 * l;
        float acc = 0.f;
        #pragma unroll
        for (int k = 0; k < 8; ++k) {
            float4 z4 = *(const float4*)(zb + k * 128);
            acc += g[k].x * z4.x + g[k].y * z4.y + g[k].z * z4.z + g[k].w * z4.w;
        }
        #pragma unroll
        for (int off = 16; off > 0; off >>= 1)
            acc += __shfl_down_sync(0xffffffffu, acc, off);
        if (l == 0) g_w[(b * OUTD + j) * EIG + e] = acc;
    }
}

// ---------------------------------------------------------------------------
// Phase 3 (R9-proven, 38.3us): out[b,n,j] = sum_e V[n,e] * w[b,j,e]
// Lane owns j-pair; w-cache (16 ull) built from swt smem transpose (coalesced
// g_w read). grid (50, BATCH), 256 thr = 8 warps; warp = 50 consecutive n.
// ---------------------------------------------------------------------------
#define NTILE2 400
__global__ void __launch_bounds__(256, 4) k_output(const float* __restrict__ V,
                                                   float* __restrict__ out) {
    const int tile = blockIdx.x, b = blockIdx.y;
    const int t = threadIdx.x;
    const int lane = t & 31, wid = t >> 5;

    __shared__ __align__(16) float swt[EIG][66];            // w transposed [e][j]
    __shared__ __align__(16) float vt[NTILE2 * EIG];        // 25.6 KB [n][e]

    const int n0 = tile * NTILE2;

    // g_w[b][j][e] -> swt[e][j]  (coalesced read, scattered smem write)
    for (int k = t; k < OUTD * EIG; k += 256)
        swt[k & 15][k >> 4] = g_w[b * (OUTD * EIG) + k];
    // V rows n0..n0+399 -> vt[n][e]  (NODES = 50*400 exactly; no bounds)
    for (int k = t; k < NTILE2 * EIG / 4; k += 256)
        *(float4*)&vt[k * 4] = *(const float4*)&V[(size_t)n0 * EIG + k * 4];
    __syncthreads();

    // one-time: lane's j-pair (2*lane, 2*lane+1) cached packed: 16 ull
    unsigned long long wp[EIG];
    #pragma unroll
    for (int e = 0; e < EIG; ++e) {
        float2 wv = *(const float2*)&swt[e][lane * 2];
        wp[e] = pack2(wv.x, wv.y);
    }

    const int nw0 = wid * 50;
    float* ob = out + ((size_t)b * NODES + n0 + nw0) * OUTD + lane * 2;

    for (int s = 0; s < 50; ++s) {
        const float* vp = &vt[(nw0 + s) * EIG];
        unsigned long long a0 = pack2(0.f, 0.f), a1 = pack2(0.f, 0.f);

        float4 va = *(const float4*)(vp);
        a0 = fma2(pack2(va.x, va.x), wp[0], a0);
        a1 = fma2(pack2(va.y, va.y), wp[1], a1);
        a0 = fma2(pack2(va.z, va.z), wp[2], a0);
        a1 = fma2(pack2(va.w, va.w), wp[3], a1);
        float4 vb = *(const float4*)(vp + 4);
        a0 = fma2(pack2(vb.x, vb.x), wp[4], a0);
        a1 = fma2(pack2(vb.y, vb.y), wp[5], a1);
        a0 = fma2(pack2(vb.z, vb.z), wp[6], a0);
        a1 = fma2(pack2(vb.w, vb.w), wp[7], a1);
        float4 vc = *(const float4*)(vp + 8);
        a0 = fma2(pack2(vc.x, vc.x), wp[8], a0);
        a1 = fma2(pack2(vc.y, vc.y), wp[9], a1);
        a0 = fma2(pack2(vc.z, vc.z), wp[10], a0);
        a1 = fma2(pack2(vc.w, vc.w), wp[11], a1);
        float4 vd = *(const float4*)(vp + 12);
        a0 = fma2(pack2(vd.x, vd.x), wp[12], a0);
        a1 = fma2(pack2(vd.y, vd.y), wp[13], a1);
        a0 = fma2(pack2(vd.z, vd.z), wp[14], a0);
        a1 = fma2(pack2(vd.w, vd.w), wp[15], a1);

        float x0, x1, y0, y1;
        unpack2(a0, x0, x1);
        unpack2(a1, y0, y1);
        *(float2*)(ob + (size_t)s * OUTD) = make_float2(x0 + y0, x1 + y1);
    }
}

extern "C" void kernel_launch(void* const* d_in, const int* in_sizes, int n_in,
                              void* d_out, int out_size) {
    const float* x = (const float*)d_in[0];   // (32, 20000, 64)
    const float* V = (const float*)d_in[1];   // (20000, 16)
    const float* G = (const float*)d_in[2];   // (64, 64, 16, 16)
    float* out = (float*)d_out;               // (32, 20000, 64)

    // no nops: ncu capture (6th process launch) lands on k_output
    k_project<<<dim3(BATCH, CBLK), 256>>>(x, V);
    k_reduce<<<256, 128>>>();
    k_filter<<<dim3(OUTD, 2), 512>>>(G);
    k_output<<<dim3(CBLK, BATCH), 256>>>(V, out);
}

// round 12
// speedup vs baseline: 1.1841x; 1.0283x over previous
#include <cuda_runtime.h>
#include <cstdint>

#define NODES 20000
#define BATCH 32
#define FEAT  64
#define OUTD  64
#define EIG   16

// --- phase-1 pipeline geometry (R7/R11-proven) ---
#define CBLK    50            // node-chunks (grid.y)
#define MPB     400           // m per block  (CBLK*MPB == NODES)
#define MT      40            // m per pipeline stage
#define NSTG    3             // stages resident
#define NSTAGES (MPB / MT)    // 10

// Scratch (device globals — no allocation allowed)
__device__ float g_zpart[CBLK * BATCH * FEAT * EIG];  // 6.55 MB partials
__device__ float g_z[BATCH * FEAT * EIG];             // 128 KB
__device__ float g_w[BATCH * OUTD * EIG];             // 128 KB

__device__ __forceinline__ uint32_t s2u(const void* p) {
    return (uint32_t)__cvta_generic_to_shared(p);
}
// ---- packed f32x2 helpers ----
__device__ __forceinline__ unsigned long long pack2(float a, float b) {
    unsigned long long r;
    asm("mov.b64 %0, {%1, %2};" : "=l"(r) : "f"(a), "f"(b));
    return r;
}
__device__ __forceinline__ void unpack2(unsigned long long v, float& a, float& b) {
    asm("mov.b64 {%0, %1}, %2;" : "=f"(a), "=f"(b) : "l"(v));
}
__device__ __forceinline__ unsigned long long fma2(unsigned long long a,
                                                   unsigned long long b,
                                                   unsigned long long c) {
    unsigned long long d;
    asm("fma.rn.f32x2 %0, %1, %2, %3;" : "=l"(d) : "l"(a), "l"(b), "l"(c));
    return d;
}
// ---- PDL primitives ----
__device__ __forceinline__ void pdl_wait() {
    asm volatile("griddepcontrol.wait;" ::: "memory");
}
__device__ __forceinline__ void pdl_launch_dependents() {
    asm volatile("griddepcontrol.launch_dependents;" ::: "memory");
}

// ---------------------------------------------------------------------------
// Phase 1 (R11-proven, ~44us): z[b,i,f] = sum_m V[m,f] * x[b,m,i]
// cp.async pipeline + FFMA2; __launch_bounds__(256,4) reg cap.
// ---------------------------------------------------------------------------
__global__ void __launch_bounds__(256, 4) k_project(const float* __restrict__ x,
                                                    const float* __restrict__ V) {
    __shared__ __align__(16) float sbuf[NSTG * MT * FEAT + NSTG * MT * EIG]; // 38.4 KB
    float* sx = sbuf;                          // [NSTG][MT][FEAT]
    float* sv = sbuf + NSTG * MT * FEAT;       // [NSTG][MT][EIG]

    const int b = blockIdx.x, c = blockIdx.y;
    const int t  = threadIdx.x;
    const int i4 = t & 15;
    const int fh = (t >> 4) & 1;
    const int mg = t >> 5;

    const int m0 = c * MPB;
    const float* xbase = x + ((size_t)b * NODES + m0) * FEAT;
    const float* vbase = V + (size_t)m0 * EIG;

    auto load_stage = [&](int s) {
        const int st = s % NSTG;
        const int mb = s * MT;
        #pragma unroll
        for (int q = t; q < MT * FEAT / 4; q += 256) {
            const int m = q >> 4, iq = q & 15;
            const float* src = xbase + (size_t)(mb + m) * FEAT + iq * 4;
            uint32_t dst = s2u(&sx[(st * MT + m) * FEAT + iq * 4]);
            asm volatile("cp.async.cg.shared.global [%0], [%1], 16;\n"
                         :: "r"(dst), "l"(src));
        }
        if (t < MT * EIG / 4) {
            const int m = t >> 2, e4 = t & 3;
            const float* src = vbase + (mb + m) * EIG + e4 * 4;
            uint32_t dst = s2u(&sv[(st * MT + m) * EIG + e4 * 4]);
            asm volatile("cp.async.cg.shared.global [%0], [%1], 16;\n"
                         :: "r"(dst), "l"(src));
        }
    };

    unsigned long long acc2[4][4];
    #pragma unroll
    for (int a = 0; a < 4; ++a)
        #pragma unroll
        for (int p = 0; p < 4; ++p) acc2[a][p] = pack2(0.f, 0.f);

    #pragma unroll
    for (int s = 0; s < NSTG - 1; ++s) {
        load_stage(s);
        asm volatile("cp.async.commit_group;\n");
    }

    for (int s = 0; s < NSTAGES; ++s) {
        if (s + NSTG - 1 < NSTAGES) load_stage(s + NSTG - 1);
        asm volatile("cp.async.commit_group;\n");
        asm volatile("cp.async.wait_group %0;\n" :: "n"(NSTG - 1));
        __syncthreads();

        const int st = s % NSTG;
        #pragma unroll
        for (int mm = 0; mm < MT / 8; ++mm) {
            const int m = mg * (MT / 8) + mm;
            float4 x4 = *(const float4*)&sx[(st * MT + m) * FEAT + i4 * 4];
            ulonglong2 va = *(const ulonglong2*)&sv[(st * MT + m) * EIG + fh * 8];
            unsigned long long xd0 = pack2(x4.x, x4.x);
            unsigned long long xd1 = pack2(x4.y, x4.y);
            unsigned long long xd2 = pack2(x4.z, x4.z);
            unsigned long long xd3 = pack2(x4.w, x4.w);
            acc2[0][0] = fma2(xd0, va.x, acc2[0][0]);
            acc2[0][1] = fma2(xd0, va.y, acc2[0][1]);
            acc2[1][0] = fma2(xd1, va.x, acc2[1][0]);
            acc2[1][1] = fma2(xd1, va.y, acc2[1][1]);
            acc2[2][0] = fma2(xd2, va.x, acc2[2][0]);
            acc2[2][1] = fma2(xd2, va.y, acc2[2][1]);
            acc2[3][0] = fma2(xd3, va.x, acc2[3][0]);
            acc2[3][1] = fma2(xd3, va.y, acc2[3][1]);
            ulonglong2 vb = *(const ulonglong2*)&sv[(st * MT + m) * EIG + fh * 8 + 4];
            acc2[0][2] = fma2(xd0, vb.x, acc2[0][2]);
            acc2[0][3] = fma2(xd0, vb.y, acc2[0][3]);
            acc2[1][2] = fma2(xd1, vb.x, acc2[1][2]);
            acc2[1][3] = fma2(xd1, vb.y, acc2[1][3]);
            acc2[2][2] = fma2(xd2, vb.x, acc2[2][2]);
            acc2[2][3] = fma2(xd2, vb.y, acc2[2][3]);
            acc2[3][2] = fma2(xd3, vb.x, acc2[3][2]);
            acc2[3][3] = fma2(xd3, vb.y, acc2[3][3]);
        }
        __syncthreads();
    }

    // dependents (k_reduce) may spin up while epilogues drain
    pdl_launch_dependents();

    // cross-mg reduction: overlay 8 x 1024 floats on sbuf
    asm volatile("cp.async.wait_group 0;\n");
    __syncthreads();
    #pragma unroll
    for (int a = 0; a < 4; ++a)
        #pragma unroll
        for (int p = 0; p < 4; ++p) {
            float lo, hi;
            unpack2(acc2[a][p], lo, hi);
            *(float2*)&sbuf[mg * 1024 + (4 * i4 + a) * EIG + fh * 8 + 2 * p] =
                make_float2(lo, hi);
        }
    __syncthreads();

    const int o = t * 4;
    float4 r = make_float4(0.f, 0.f, 0.f, 0.f);
    #pragma unroll
    for (int g2 = 0; g2 < 8; ++g2) {
        float4 p = *(const float4*)&sbuf[g2 * 1024 + o];
        r.x += p.x; r.y += p.y; r.z += p.z; r.w += p.w;
    }
    *(float4*)&g_zpart[((size_t)c * BATCH + b) * 1024 + o] = r;
}

// ---------------------------------------------------------------------------
// Reduce chunk partials: z = sum_c zpart[c]   (6.55 MB, L2-resident)
// PDL: release filter immediately (its G gather is independent of z).
// ---------------------------------------------------------------------------
__global__ void __launch_bounds__(128) k_reduce() {
    pdl_launch_dependents();
    pdl_wait();   // zpart must be complete
    const int idx = blockIdx.x * 128 + threadIdx.x;  // 32768 threads total
    float s = 0.f;
    #pragma unroll 10
    for (int c = 0; c < CBLK; ++c)
        s += g_zpart[c * (BATCH * FEAT * EIG) + idx];
    g_z[idx] = s;
}

// ---------------------------------------------------------------------------
// Phase 2 (R6-proven compute): w[b,j,e] = sum_n G-interleaved * z.
// PDL: G register gather (independent) BEFORE pdl_wait -> overlaps k_reduce.
// ---------------------------------------------------------------------------
__global__ void __launch_bounds__(512) k_filter(const float* __restrict__ G) {
    const int j  = blockIdx.x;
    const int bh = blockIdx.y;
    const int e  = threadIdx.x >> 5;
    const int l  = threadIdx.x & 31;

    const float* Gp = G + (size_t)j * (FEAT * EIG * EIG)
                        + (l >> 2) * (EIG * EIG) + e * EIG + (l & 3) * 4;
    float4 g[8];
    #pragma unroll
    for (int k = 0; k < 8; ++k)
        g[k] = *(const float4*)(Gp + k * 8 * (EIG * EIG));

    // G cached; release k_output (its V-tile fill is independent of w)
    pdl_launch_dependents();
    pdl_wait();   // z must be complete

    const int b0 = bh * 16;
    #pragma unroll 2
    for (int bb = 0; bb < 16; ++bb) {
        const int b = b0 + bb;
        const float* zb = g_z + b * (FEAT * EIG) + 4 * l;
        float acc = 0.f;
        #pragma unroll
        for (int k = 0; k < 8; ++k) {
            float4 z4 = *(const float4*)(zb + k * 128);
            acc += g[k].x * z4.x + g[k].y * z4.y + g[k].z * z4.z + g[k].w * z4.w;
        }
        #pragma unroll
        for (int off = 16; off > 0; off >>= 1)
            acc += __shfl_down_sync(0xffffffffu, acc, off);
        if (l == 0) g_w[(b * OUTD + j) * EIG + e] = acc;
    }
}

// ---------------------------------------------------------------------------
// Phase 3 (R9/R11-proven compute, 38.3us): out[b,n,j] = sum_e V[n,e]*w[b,j,e]
// PDL: vt fill from V (independent) BEFORE pdl_wait -> overlaps k_filter;
// then swt fill from g_w after the wait.
// ---------------------------------------------------------------------------
#define NTILE2 400
__global__ void __launch_bounds__(256, 4) k_output(const float* __restrict__ V,
                                                   float* __restrict__ out) {
    const int tile = blockIdx.x, b = blockIdx.y;
    const int t = threadIdx.x;
    const int lane = t & 31, wid = t >> 5;

    __shared__ __align__(16) float swt[EIG][66];            // w transposed [e][j]
    __shared__ __align__(16) float vt[NTILE2 * EIG];        // 25.6 KB [n][e]

    const int n0 = tile * NTILE2;

    // independent prologue: V rows n0..n0+399 -> vt[n][e]
    for (int k = t; k < NTILE2 * EIG / 4; k += 256)
        *(float4*)&vt[k * 4] = *(const float4*)&V[(size_t)n0 * EIG + k * 4];

    pdl_wait();   // w must be complete

    // g_w[b][j][e] -> swt[e][j]  (coalesced read, scattered smem write)
    for (int k = t; k < OUTD * EIG; k += 256)
        swt[k & 15][k >> 4] = g_w[b * (OUTD * EIG) + k];
    __syncthreads();

    // lane's j-pair (2*lane, 2*lane+1) cached packed: 16 ull
    unsigned long long wp[EIG];
    #pragma unroll
    for (int e = 0; e < EIG; ++e) {
        float2 wv = *(const float2*)&swt[e][lane * 2];
        wp[e] = pack2(wv.x, wv.y);
    }

    const int nw0 = wid * 50;
    float* ob = out + ((size_t)b * NODES + n0 + nw0) * OUTD + lane * 2;

    for (int s = 0; s < 50; ++s) {
        const float* vp = &vt[(nw0 + s) * EIG];
        unsigned long long a0 = pack2(0.f, 0.f), a1 = pack2(0.f, 0.f);

        float4 va = *(const float4*)(vp);
        a0 = fma2(pack2(va.x, va.x), wp[0], a0);
        a1 = fma2(pack2(va.y, va.y), wp[1], a1);
        a0 = fma2(pack2(va.z, va.z), wp[2], a0);
        a1 = fma2(pack2(va.w, va.w), wp[3], a1);
        float4 vb = *(const float4*)(vp + 4);
        a0 = fma2(pack2(vb.x, vb.x), wp[4], a0);
        a1 = fma2(pack2(vb.y, vb.y), wp[5], a1);
        a0 = fma2(pack2(vb.z, vb.z), wp[6], a0);
        a1 = fma2(pack2(vb.w, vb.w), wp[7], a1);
        float4 vc = *(const float4*)(vp + 8);
        a0 = fma2(pack2(vc.x, vc.x), wp[8], a0);
        a1 = fma2(pack2(vc.y, vc.y), wp[9], a1);
        a0 = fma2(pack2(vc.z, vc.z), wp[10], a0);
        a1 = fma2(pack2(vc.w, vc.w), wp[11], a1);
        float4 vd = *(const float4*)(vp + 12);
        a0 = fma2(pack2(vd.x, vd.x), wp[12], a0);
        a1 = fma2(pack2(vd.y, vd.y), wp[13], a1);
        a0 = fma2(pack2(vd.z, vd.z), wp[14], a0);
        a1 = fma2(pack2(vd.w, vd.w), wp[15], a1);

        float x0, x1, y0, y1;
        unpack2(a0, x0, x1);
        unpack2(a1, y0, y1);
        *(float2*)(ob + (size_t)s * OUTD) = make_float2(x0 + y0, x1 + y1);
    }
}

extern "C" void kernel_launch(void* const* d_in, const int* in_sizes, int n_in,
                              void* d_out, int out_size) {
    const float* x = (const float*)d_in[0];   // (32, 20000, 64)
    const float* V = (const float*)d_in[1];   // (20000, 16)
    const float* G = (const float*)d_in[2];   // (64, 64, 16, 16)
    float* out = (float*)d_out;               // (32, 20000, 64)

    // first kernel: normal launch
    k_project<<<dim3(BATCH, CBLK), 256>>>(x, V);

    // downstream kernels: PDL (programmatic stream serialization)
    cudaLaunchAttribute pdlAttr;
    pdlAttr.id = cudaLaunchAttributeProgrammaticStreamSerialization;
    pdlAttr.val.programmaticStreamSerializationAllowed = 1;

    {
        cudaLaunchConfig_t cfg = {};
        cfg.gridDim = dim3(256);
        cfg.blockDim = dim3(128);
        cfg.attrs = &pdlAttr;
        cfg.numAttrs = 1;
        cudaLaunchKernelEx(&cfg, k_reduce);
    }
    {
        cudaLaunchConfig_t cfg = {};
        cfg.gridDim = dim3(OUTD, 2);
        cfg.blockDim = dim3(512);
        cfg.attrs = &pdlAttr;
        cfg.numAttrs = 1;
        cudaLaunchKernelEx(&cfg, k_filter, G);
    }
    {
        cudaLaunchConfig_t cfg = {};
        cfg.gridDim = dim3(CBLK, BATCH);
        cfg.blockDim = dim3(256);
        cfg.attrs = &pdlAttr;
        cfg.numAttrs = 1;
        cudaLaunchKernelEx(&cfg, k_output, V, out);
    }
}